// round 13
// baseline (speedup 1.0000x reference)
#include <cuda_runtime.h>
#include <cstdint>

// Problem shape (fixed for this dataset entry)
#define BB 8
#define CC 81
#define HH 96
#define WW 320
#define NN 16
#define HWSZ (HH * WW)            // 30720
#define TPB 256                   // 128 pixels/block, 2 channel-groups
#define PXB 128                   // pixels per block
#define BATCH 9
#define CSPLIT 45                 // group A: ch [0,45) = 5 batches; group B: ch [45,81) = 4 batches
#define NBLK (BB * HWSZ / PXB)    // 1920 blocks

#define ALPHA_F   0.25f
#define FG_W_F    13.0f
#define BG_W_F    1.0f
#define DEPTH_MIN_F 0.001f
#define DEPTH_MAX_F 60.0f
#define NUM_BINS_I  80

// Cross-block accumulator (zero at load; last block resets -> deterministic per replay)
__device__ float    g_scratch = 0.0f;
__device__ unsigned g_count   = 0u;

__global__ __launch_bounds__(TPB, 6) void ddn_loss_kernel(
    const float* __restrict__ logits,   // (B,C,H,W)
    const float* __restrict__ boxes,    // (B*N,4)
    const float* __restrict__ depths,   // (B*N,)
    float* __restrict__ out)            // scalar
{
    __shared__ int   sbu1[NN], sbv1[NN], sbu2[NN], sbv2[NN];
    __shared__ float sdep[NN];
    __shared__ float sA[PXB];           // group-A partial sum-exp per pixel
    __shared__ float sred[8];

    const int t    = threadIdx.x;
    const int half = t >> 7;            // 0: ch[0,45), 1: ch[45,81)
    const int lt   = t & (PXB - 1);     // pixel slot within block
    const int g    = blockIdx.x * PXB + lt;      // pixel id (0..245759)
    const int b    = g / HWSZ;                   // block never crosses batch (30720 % 128 == 0)
    const int rem  = g - b * HWSZ;
    const int h    = rem / WW;
    const int w    = rem - h * WW;

    // Channel-group base for this thread
    const int cbase = half ? CSPLIT : 0;
    const int nb    = half ? (CC - CSPLIT) / BATCH : CSPLIT / BATCH;   // 4 or 5
    const float* __restrict__ gsrc =
        logits + (size_t)b * CC * HWSZ + (size_t)cbase * HWSZ + rem;

    // ---- Kick off the first batch of channel loads immediately ----
    float cur[BATCH], nxt[BATCH];
#pragma unroll
    for (int i = 0; i < BATCH; i++)
        cur[i] = gsrc[(size_t)i * HWSZ];

    if (t < NN) {
        const int i = b * NN + t;
        sbu1[t] = (int)floorf(boxes[4 * i + 0]);
        sbv1[t] = (int)floorf(boxes[4 * i + 1]);
        sbu2[t] = (int)ceilf (boxes[4 * i + 2]);
        sbv2[t] = (int)ceilf (boxes[4 * i + 3]);
        sdep[t] = depths[i];
    }
    __syncthreads();

    // ---- Rasterize + LID binning: only group B (it finishes the loss) ----
    float wgt = BG_W_F;
    float xt  = 0.f;
    if (half) {
        float dmin = 1e10f;
        bool  fg   = false;
#pragma unroll
        for (int i = 0; i < NN; i++) {
            const bool cov = (h >= sbv1[i]) & (h < sbv2[i]) &
                             (w >= sbu1[i]) & (w < sbu2[i]);
            if (cov) { fg = true; dmin = fminf(dmin, sdep[i]); }
        }
        const float d = fg ? dmin : 0.0f;
        wgt = fg ? FG_W_F : BG_W_F;
        const float bin_size = 2.0f * (DEPTH_MAX_F - DEPTH_MIN_F)
                               / ((float)NUM_BINS_I * (1.0f + (float)NUM_BINS_I));
        float idxf = -0.5f + 0.5f * sqrtf(1.0f + 8.0f * (d - DEPTH_MIN_F) / bin_size);
        if (!(idxf >= 0.0f) || idxf > (float)NUM_BINS_I) idxf = (float)NUM_BINS_I;
        const int tgt = (int)idxf;                // truncation toward zero
        // Target logit (absolute channel index; line shared with the stream)
        xt = logits[(size_t)b * CC * HWSZ + (size_t)tgt * HWSZ + rem];
    }

    // ---- Stream this group's channels: 9-deep double-buffered pipeline ----
    float s = 0.f;
#pragma unroll 1
    for (int blk = 0; blk < nb - 1; blk++) {
        const float* p = gsrc + (size_t)(blk + 1) * BATCH * HWSZ;
#pragma unroll
        for (int i = 0; i < BATCH; i++)          // issue next batch first (stays in flight)
            nxt[i] = p[(size_t)i * HWSZ];
#pragma unroll
        for (int i = 0; i < BATCH; i++)          // consume current batch
            s += __expf(cur[i]);
#pragma unroll
        for (int i = 0; i < BATCH; i++)
            cur[i] = nxt[i];
    }
#pragma unroll
    for (int i = 0; i < BATCH; i++)
        s += __expf(cur[i]);

    // ---- Combine the two channel halves per pixel ----
    if (!half) sA[lt] = s;
    __syncthreads();

    float local = 0.f;
    if (half) {
        const float stot = sA[lt] + s;
        const float lp = xt - __logf(stot);
        const float pt = __expf(lp);
        local = wgt * (-ALPHA_F * (1.f - pt) * (1.f - pt) * lp);
    }

    // ---- Block reduction (group-A threads contribute 0) ----
#pragma unroll
    for (int o = 16; o > 0; o >>= 1)
        local += __shfl_xor_sync(0xffffffffu, local, o);
    if ((t & 31) == 0) sred[t >> 5] = local;
    __syncthreads();

    // ---- Grid reduction fused into the kernel ----
    if (t == 0) {
        float v = 0.f;
#pragma unroll
        for (int i = 0; i < 8; i++) v += sred[i];
        atomicAdd(&g_scratch, v);
        __threadfence();
        const unsigned ticket = atomicAdd(&g_count, 1u);
        if (ticket == (unsigned)(gridDim.x - 1)) {
            // All prior scratch adds are visible (fence before ticket).
            const float tot = atomicAdd(&g_scratch, 0.0f);   // coherent read
            const float inv_np = 1.0f / (float)(BB * HH * WW);
            out[0] = tot * inv_np;
            // Reset for the next graph replay: deterministic invariant.
            g_scratch = 0.0f;
            __threadfence();
            g_count = 0u;
        }
    }
}

extern "C" void kernel_launch(void* const* d_in, const int* in_sizes, int n_in,
                              void* d_out, int out_size) {
    const float* logits = (const float*)d_in[0];   // depth_logits (B,C,H,W) f32
    const float* boxes  = (const float*)d_in[1];   // gt_boxes2d (B*N,4) f32
    // d_in[2] = num_gt_per_img (scalar int, constant 16 for this shape)
    const float* depths = (const float*)d_in[3];   // gt_center_depth (B*N,) f32
    float* out = (float*)d_out;

    ddn_loss_kernel<<<NBLK, TPB>>>(logits, boxes, depths, out);
}

// round 15
// speedup vs baseline: 1.0019x; 1.0019x over previous
#include <cuda_runtime.h>
#include <cstdint>

// Problem shape (fixed for this dataset entry)
#define BB 8
#define CC 81
#define HH 96
#define WW 320
#define NN 16
#define HWSZ (HH * WW)            // 30720
#define TOTALPX (BB * HWSZ)       // 245760
#define TPB 128
#define GRID (148 * 12)           // 1776 blocks = exactly one wave at 12 CTA/SM
#define STRIDE (GRID * TPB)       // 227328 threads; first 18432 do a 2nd pixel
#define BATCH 9                   // 81 = 9*9

#define ALPHA_F   0.25f
#define FG_W_F    13.0f
#define BG_W_F    1.0f
#define DEPTH_MIN_F 0.001f
#define DEPTH_MAX_F 60.0f
#define NUM_BINS_I  80

// Cross-block accumulator (zero at load; last block resets -> deterministic per replay)
__device__ float    g_scratch = 0.0f;
__device__ unsigned g_count   = 0u;

__global__ __launch_bounds__(TPB, 12) void ddn_loss_kernel(
    const float* __restrict__ logits,   // (B,C,H,W)
    const float* __restrict__ boxes,    // (B*N,4)
    const float* __restrict__ depths,   // (B*N,)
    float* __restrict__ out)            // scalar
{
    // Boxes for ALL 8 images, pre-binned once -> barrier-free pixel loop
    __shared__ int   sbu1[BB * NN], sbv1[BB * NN], sbu2[BB * NN], sbv2[BB * NN];
    __shared__ float sdep[BB * NN];
    __shared__ float sred[4];

    const int t = threadIdx.x;
    const int g = blockIdx.x * TPB + t;

    // TPB == BB*NN == 128: each thread preps exactly one box
    {
        sbu1[t] = (int)floorf(boxes[4 * t + 0]);
        sbv1[t] = (int)floorf(boxes[4 * t + 1]);
        sbu2[t] = (int)ceilf (boxes[4 * t + 2]);
        sbv2[t] = (int)ceilf (boxes[4 * t + 3]);
        sdep[t] = depths[t];
    }
    __syncthreads();

    float local = 0.f;

    // Grid-stride over pixels: 1 iteration for most threads, 2 for the first 18432.
    for (int px = g; px < TOTALPX; px += STRIDE) {
        const int b   = px / HWSZ;
        const int rem = px - b * HWSZ;
        const int h   = rem / WW;
        const int w   = rem - h * WW;

        // Base of this pixel within batch b's plane stack; start the first
        // batch of channel loads immediately so they fly during rasterization.
        const float* __restrict__ gsrc = logits + (size_t)b * CC * HWSZ + rem;
        float cur[BATCH], nxt[BATCH];
#pragma unroll
        for (int i = 0; i < BATCH; i++)
            cur[i] = gsrc[(size_t)i * HWSZ];

        // ---- Rasterize + LID binning (smem broadcast: all lanes same b) ----
        const int bo = b * NN;
        float dmin = 1e10f;
        bool  fg   = false;
#pragma unroll
        for (int i = 0; i < NN; i++) {
            const bool cov = (h >= sbv1[bo + i]) & (h < sbv2[bo + i]) &
                             (w >= sbu1[bo + i]) & (w < sbu2[bo + i]);
            if (cov) { fg = true; dmin = fminf(dmin, sdep[bo + i]); }
        }
        const float d   = fg ? dmin : 0.0f;
        const float wgt = fg ? FG_W_F : BG_W_F;
        const float bin_size = 2.0f * (DEPTH_MAX_F - DEPTH_MIN_F)
                               / ((float)NUM_BINS_I * (1.0f + (float)NUM_BINS_I));
        float idxf = -0.5f + 0.5f * sqrtf(1.0f + 8.0f * (d - DEPTH_MIN_F) / bin_size);
        if (!(idxf >= 0.0f) || idxf > (float)NUM_BINS_I) idxf = (float)NUM_BINS_I;
        const int tgt = (int)idxf;                // truncation toward zero

        // Target logit (line also touched by the stream)
        const float xt = gsrc[(size_t)tgt * HWSZ];

        // ---- Stream 81 channels: 9-deep double-buffered pipeline (R7 body) ----
        float s = 0.f;
#pragma unroll 1
        for (int blk = 0; blk < CC / BATCH - 1; blk++) {
            const float* p = gsrc + (size_t)(blk + 1) * BATCH * HWSZ;
#pragma unroll
            for (int i = 0; i < BATCH; i++)      // issue next batch first
                nxt[i] = p[(size_t)i * HWSZ];
#pragma unroll
            for (int i = 0; i < BATCH; i++)      // consume current batch
                s += __expf(cur[i]);
#pragma unroll
            for (int i = 0; i < BATCH; i++)
                cur[i] = nxt[i];
        }
#pragma unroll
        for (int i = 0; i < BATCH; i++)
            s += __expf(cur[i]);

        // ---- Focal loss, weighted ----
        const float lp = xt - __logf(s);
        const float pt = __expf(lp);
        local += wgt * (-ALPHA_F * (1.f - pt) * (1.f - pt) * lp);
    }

    // ---- Block reduction (4 warps) ----
#pragma unroll
    for (int o = 16; o > 0; o >>= 1)
        local += __shfl_xor_sync(0xffffffffu, local, o);
    if ((t & 31) == 0) sred[t >> 5] = local;
    __syncthreads();

    // ---- Grid reduction fused into the kernel ----
    if (t == 0) {
        const float v = sred[0] + sred[1] + sred[2] + sred[3];
        atomicAdd(&g_scratch, v);
        __threadfence();
        const unsigned ticket = atomicAdd(&g_count, 1u);
        if (ticket == (unsigned)(GRID - 1)) {
            // All prior scratch adds are visible (fence before ticket).
            const float tot = atomicAdd(&g_scratch, 0.0f);   // coherent read
            const float inv_np = 1.0f / (float)TOTALPX;
            out[0] = tot * inv_np;
            // Reset for the next graph replay: deterministic invariant.
            g_scratch = 0.0f;
            __threadfence();
            g_count = 0u;
        }
    }
}

extern "C" void kernel_launch(void* const* d_in, const int* in_sizes, int n_in,
                              void* d_out, int out_size) {
    const float* logits = (const float*)d_in[0];   // depth_logits (B,C,H,W) f32
    const float* boxes  = (const float*)d_in[1];   // gt_boxes2d (B*N,4) f32
    // d_in[2] = num_gt_per_img (scalar int, constant 16 for this shape)
    const float* depths = (const float*)d_in[3];   // gt_center_depth (B*N,) f32
    float* out = (float*)d_out;

    ddn_loss_kernel<<<GRID, TPB>>>(logits, boxes, depths, out);
}

// round 16
// speedup vs baseline: 1.1577x; 1.1555x over previous
#include <cuda_runtime.h>
#include <cstdint>

// Problem shape (fixed for this dataset entry)
#define BB 8
#define CC 81
#define HH 96
#define WW 320
#define NN 16
#define HWSZ (HH * WW)            // 30720
#define TPB 256
#define BATCH 9                   // 81 = 9*9
#define NROUND (CC / BATCH)       // 9
#define NBLK (BB * HWSZ / TPB)    // 960 blocks, 1 px/thread

#define ALPHA_F   0.25f
#define FG_W_F    13.0f
#define BG_W_F    1.0f
#define DEPTH_MIN_F 0.001f
#define DEPTH_MAX_F 60.0f
#define NUM_BINS_I  80

// Cross-block accumulator (zero at load; last block resets -> deterministic per replay)
__device__ float    g_scratch = 0.0f;
__device__ unsigned g_count   = 0u;

__global__ __launch_bounds__(TPB, 5) void ddn_loss_kernel(
    const float* __restrict__ logits,   // (B,C,H,W)
    const float* __restrict__ boxes,    // (B*N,4)
    const float* __restrict__ depths,   // (B*N,)
    float* __restrict__ out)            // scalar
{
    __shared__ int   sbu1[NN], sbv1[NN], sbu2[NN], sbv2[NN];
    __shared__ float sdep[NN];
    __shared__ float sred[8];

    const int t   = threadIdx.x;
    const int g   = blockIdx.x * TPB + t;        // one pixel per thread
    const int b   = g / HWSZ;                    // block never crosses batch (30720 % 256 == 0)
    const int rem = g - b * HWSZ;
    const int h   = rem / WW;
    const int w   = rem - h * WW;

    // Base of this pixel within batch b's plane stack.
    const float* __restrict__ gsrc = logits + (size_t)b * CC * HWSZ + rem;

    // ---- Prologue: put TWO batches (18 loads) in flight before any ALU ----
    float cur[BATCH], nxt[BATCH];
#pragma unroll
    for (int i = 0; i < BATCH; i++)
        cur[i] = gsrc[(size_t)i * HWSZ];
#pragma unroll
    for (int i = 0; i < BATCH; i++)
        nxt[i] = gsrc[(size_t)(BATCH + i) * HWSZ];

    if (t < NN) {
        const int i = b * NN + t;
        sbu1[t] = (int)floorf(boxes[4 * i + 0]);
        sbv1[t] = (int)floorf(boxes[4 * i + 1]);
        sbu2[t] = (int)ceilf (boxes[4 * i + 2]);
        sbv2[t] = (int)ceilf (boxes[4 * i + 3]);
        sdep[t] = depths[i];
    }
    __syncthreads();

    // ---- Rasterize + LID binning (overlaps with the 18 in-flight loads) ----
    float dmin = 1e10f;
    bool  fg   = false;
#pragma unroll
    for (int i = 0; i < NN; i++) {
        const bool cov = (h >= sbv1[i]) & (h < sbv2[i]) &
                         (w >= sbu1[i]) & (w < sbu2[i]);
        if (cov) { fg = true; dmin = fminf(dmin, sdep[i]); }
    }
    const float d   = fg ? dmin : 0.0f;
    const float wgt = fg ? FG_W_F : BG_W_F;
    const float bin_size = 2.0f * (DEPTH_MAX_F - DEPTH_MIN_F)
                           / ((float)NUM_BINS_I * (1.0f + (float)NUM_BINS_I));
    float idxf = -0.5f + 0.5f * sqrtf(1.0f + 8.0f * (d - DEPTH_MIN_F) / bin_size);
    if (!(idxf >= 0.0f) || idxf > (float)NUM_BINS_I) idxf = (float)NUM_BINS_I;
    const int tgt = (int)idxf;                    // truncation toward zero

    // Target logit (line also touched by the stream)
    const float xt = gsrc[(size_t)tgt * HWSZ];

    // ---- Stream 81 channels: 9-deep pipeline, prefetch distance 2 ----
    float s = 0.f;
#pragma unroll 1
    for (int r = 0; r < NROUND - 2; r++) {
        const float* p = gsrc + (size_t)(r + 2) * BATCH * HWSZ;
        float tmp[BATCH];
#pragma unroll
        for (int i = 0; i < BATCH; i++)          // issue batch r+2 (2 batches stay in flight)
            tmp[i] = p[(size_t)i * HWSZ];
#pragma unroll
        for (int i = 0; i < BATCH; i++)          // consume batch r
            s += __expf(cur[i]);
#pragma unroll
        for (int i = 0; i < BATCH; i++) {        // rotate buffers
            cur[i] = nxt[i];
            nxt[i] = tmp[i];
        }
    }
#pragma unroll
    for (int i = 0; i < BATCH; i++)              // drain batch 7
        s += __expf(cur[i]);
#pragma unroll
    for (int i = 0; i < BATCH; i++)              // drain batch 8
        s += __expf(nxt[i]);

    // ---- Focal loss, weighted ----
    const float lp = xt - __logf(s);
    const float pt = __expf(lp);
    float local = wgt * (-ALPHA_F * (1.f - pt) * (1.f - pt) * lp);

    // ---- Block reduction ----
#pragma unroll
    for (int o = 16; o > 0; o >>= 1)
        local += __shfl_xor_sync(0xffffffffu, local, o);
    if ((t & 31) == 0) sred[t >> 5] = local;
    __syncthreads();

    // ---- Grid reduction fused into the kernel ----
    if (t == 0) {
        float v = 0.f;
#pragma unroll
        for (int i = 0; i < 8; i++) v += sred[i];
        atomicAdd(&g_scratch, v);
        __threadfence();
        const unsigned ticket = atomicAdd(&g_count, 1u);
        if (ticket == (unsigned)(gridDim.x - 1)) {
            // All prior scratch adds are visible (fence before ticket).
            const float tot = atomicAdd(&g_scratch, 0.0f);   // coherent read
            const float inv_np = 1.0f / (float)(BB * HH * WW);
            out[0] = tot * inv_np;
            // Reset for the next graph replay: deterministic invariant.
            g_scratch = 0.0f;
            __threadfence();
            g_count = 0u;
        }
    }
}

extern "C" void kernel_launch(void* const* d_in, const int* in_sizes, int n_in,
                              void* d_out, int out_size) {
    const float* logits = (const float*)d_in[0];   // depth_logits (B,C,H,W) f32
    const float* boxes  = (const float*)d_in[1];   // gt_boxes2d (B*N,4) f32
    // d_in[2] = num_gt_per_img (scalar int, constant 16 for this shape)
    const float* depths = (const float*)d_in[3];   // gt_center_depth (B*N,) f32
    float* out = (float*)d_out;

    ddn_loss_kernel<<<NBLK, TPB>>>(logits, boxes, depths, out);
}